// round 1
// baseline (speedup 1.0000x reference)
#include <cuda_runtime.h>
#include <math.h>

#define BB   8
#define CC   256
#define FDD  128
#define HWW  4096
#define POSC 34
#define IN1  384
#define TP   64

// ---------------- device-global scratch (no runtime allocation) ----------------
__device__ float g_q  [BB*HWW*CC];     // [b][p][256] row-major (queries, fused x)
__device__ float g_yf [BB*CC*HWW];     // [b][c][p]   (fused y, channel-major for dwconv)
__device__ float g_z  [BB*CC*HWW];     // [b][c][p]   (after depthwise 3x3)
__device__ float g_k  [BB*HWW*CC];     // [b][p][256] row-major (keys)
__device__ float g_pos[BB*HWW*POSC];   // [b][p][34]
__device__ float g_w1t  [IN1*CC];      // fus_w1^T  [384][256]
__device__ float g_w2t  [CC*CC];       // fus_w2^T  [256][256]
__device__ float g_pwt  [CC*CC];       // pw_w^T    [256][256]
__device__ float g_pgw1t[130*FDD];     // pg_w1^T   [130][128]
__device__ float g_pgw2t[FDD*32];      // pg_w2^T   [128][32]

// ---------------- weight transposes ----------------
__global__ void prep_weights(const float* __restrict__ fw1, const float* __restrict__ fw2,
                             const float* __restrict__ pww, const float* __restrict__ pgw1,
                             const float* __restrict__ pgw2)
{
    int i = blockIdx.x * 256 + threadIdx.x;
    if (i < 256*384) { int o = i / 384, c = i % 384; g_w1t[c*256 + o] = fw1[i]; return; }
    i -= 256*384;
    if (i < 256*256) { int o = i >> 8, c = i & 255; g_w2t[c*256 + o] = fw2[i]; return; }
    i -= 65536;
    if (i < 256*256) { int o = i >> 8, c = i & 255; g_pwt[c*256 + o] = pww[i]; return; }
    i -= 65536;
    if (i < 128*130) { int o = i / 130, c = i % 130; g_pgw1t[c*128 + o] = pgw1[i]; return; }
    i -= 16640;
    if (i < 32*128)  { int o = i >> 7, c = i & 127; g_pgw2t[c*32 + o] = pgw2[i]; return; }
}

// rank-1 update helper: acc[0..63] += w * row[0..63] (row in smem, float4 reads)
__device__ __forceinline__ void fma_row(float* acc, const float* row, float w)
{
    const float4* r4 = (const float4*)row;
#pragma unroll
    for (int j = 0; j < 16; j++) {
        float4 v = r4[j];
        acc[4*j+0] = fmaf(w, v.x, acc[4*j+0]);
        acc[4*j+1] = fmaf(w, v.y, acc[4*j+1]);
        acc[4*j+2] = fmaf(w, v.z, acc[4*j+2]);
        acc[4*j+3] = fmaf(w, v.w, acc[4*j+3]);
    }
}

// ---------------- fuser: concat(xin[256], feat[128]) -> relu(W1·)+b1 -> W2·+b2 ----------------
// mode 0: write g_q   row-major  [b][p][256]
// mode 1: write g_yf  ch-major   [b][c][p]
__global__ void fuser_kernel(const float* __restrict__ xin, const float* __restrict__ feat,
                             const float* __restrict__ b1, const float* __restrict__ b2,
                             int mode)
{
    extern __shared__ float sm[];     // input tile: 384 rows x 64 (stride 64); H tile: 256 rows stride 68
    const int b  = blockIdx.y;
    const int p0 = blockIdx.x * TP;
    const int t  = threadIdx.x;       // 256 threads

    float4* sm4 = (float4*)sm;
    for (int i = t; i < IN1*16; i += 256) {
        int c = i >> 4, j = i & 15;
        const float* src = (c < CC) ? (xin  + ((size_t)(b*CC  + c     ))*HWW + p0)
                                    : (feat + ((size_t)(b*FDD + (c-CC)))*HWW + p0);
        sm4[i] = ((const float4*)src)[j];
    }
    __syncthreads();

    float acc[TP];
    {
        float bias = b1[t];
#pragma unroll
        for (int p = 0; p < TP; p++) acc[p] = bias;
    }
    float w = g_w1t[t];
    for (int c = 0; c < IN1; c++) {
        float wn = (c + 1 < IN1) ? g_w1t[(c+1)*CC + t] : 0.f;
        fma_row(acc, sm + c*TP, w);
        w = wn;
    }
    __syncthreads();
#pragma unroll
    for (int p = 0; p < TP; p++) sm[t*68 + p] = fmaxf(acc[p], 0.f);   // H, stride 68 (conflict-light)
    __syncthreads();

    float acc2[TP];
    {
        float bias = b2[t];
#pragma unroll
        for (int p = 0; p < TP; p++) acc2[p] = bias;
    }
    w = g_w2t[t];
    for (int h = 0; h < CC; h++) {
        float wn = (h + 1 < CC) ? g_w2t[(h+1)*CC + t] : 0.f;
        fma_row(acc2, sm + h*68, w);
        w = wn;
    }

    if (mode == 0) {
#pragma unroll
        for (int p = 0; p < TP; p++)
            g_q[((size_t)(b*HWW + p0 + p))*CC + t] = acc2[p];
    } else {
        __syncthreads();
#pragma unroll
        for (int p = 0; p < TP; p++) sm[t*68 + p] = acc2[p];
        __syncthreads();
        for (int i = t; i < CC*TP; i += 256) {
            int c = i >> 6, p = i & 63;
            g_yf[((size_t)(b*CC + c))*HWW + p0 + p] = sm[c*68 + p];
        }
    }
}

// ---------------- pos_gen: inp=[gx+1, gy+1, feat2] -> relu(pgW1)+ -> relu(pgW2) ; append raw gx,gy --------
__global__ void posgen_kernel(const float* __restrict__ feat2,
                              const float* __restrict__ b1, const float* __restrict__ b2)
{
    extern __shared__ float sm[];     // input: 130 x 64 (stride 64); H: 128 rows stride 68 (8704 floats)
    const int b   = blockIdx.y;
    const int row = blockIdx.x;       // image row (tile = one row of 64 px)
    const int p0  = row * 64;
    const int t   = threadIdx.x;      // 128 threads
    const float gy = -1.f + 2.f * row * (1.f/63.f);

    for (int i = t; i < 130*64; i += 128) {
        int c = i >> 6, p = i & 63;
        float v;
        if (c == 0)      v = 1.f + (-1.f + 2.f * p * (1.f/63.f));
        else if (c == 1) v = 1.f + gy;
        else             v = feat2[((size_t)(b*FDD + (c-2)))*HWW + p0 + p];
        sm[i] = v;
    }
    __syncthreads();

    float acc[64];
    {
        float bias = b1[t];
#pragma unroll
        for (int p = 0; p < 64; p++) acc[p] = bias;
    }
    float w = g_pgw1t[t];
    for (int c = 0; c < 130; c++) {
        float wn = (c + 1 < 130) ? g_pgw1t[(c+1)*FDD + t] : 0.f;
        fma_row(acc, sm + c*64, w);
        w = wn;
    }
    __syncthreads();
#pragma unroll
    for (int p = 0; p < 64; p++) sm[t*68 + p] = fmaxf(acc[p], 0.f);
    __syncthreads();

    if (t < 32) {
        float acc2[64];
        float bias = b2[t];
#pragma unroll
        for (int p = 0; p < 64; p++) acc2[p] = bias;
        float w2 = g_pgw2t[t];
        for (int h = 0; h < FDD; h++) {
            float wn = (h + 1 < FDD) ? g_pgw2t[(h+1)*32 + t] : 0.f;
            fma_row(acc2, sm + h*68, w2);
            w2 = wn;
        }
#pragma unroll
        for (int p = 0; p < 64; p++)
            g_pos[((size_t)(b*HWW + p0 + p))*POSC + t] = fmaxf(acc2[p], 0.f);
    } else if (t == 32) {
        for (int p = 0; p < 64; p++)
            g_pos[((size_t)(b*HWW + p0 + p))*POSC + 32] = -1.f + 2.f * p * (1.f/63.f);
    } else if (t == 33) {
        for (int p = 0; p < 64; p++)
            g_pos[((size_t)(b*HWW + p0 + p))*POSC + 33] = gy;
    }
}

// ---------------- depthwise 3x3 (SAME, zero pad) on g_yf -> g_z ----------------
__global__ void dw_kernel(const float* __restrict__ dww, const float* __restrict__ dwb)
{
    __shared__ float plane[HWW];
    const int c = blockIdx.x, b = blockIdx.y, t = threadIdx.x;
    const float* src = g_yf + ((size_t)(b*CC + c))*HWW;
    float4* p4 = (float4*)plane;
    for (int i = t; i < HWW/4; i += 256) p4[i] = ((const float4*)src)[i];
    float w[9];
#pragma unroll
    for (int i = 0; i < 9; i++) w[i] = __ldg(dww + c*9 + i);
    const float bias = __ldg(dwb + c);
    __syncthreads();

    float* dst = g_z + ((size_t)(b*CC + c))*HWW;
#pragma unroll
    for (int ii = 0; ii < 16; ii++) {
        int p  = t + ii*256;
        int py = p >> 6, px = p & 63;
        float s = bias;
#pragma unroll
        for (int dy = -1; dy <= 1; dy++) {
            int iy = py + dy;
            if (iy < 0 || iy > 63) continue;
#pragma unroll
            for (int dx = -1; dx <= 1; dx++) {
                int ix = px + dx;
                if (ix < 0 || ix > 63) continue;
                s = fmaf(plane[iy*64 + ix], w[(dy+1)*3 + (dx+1)], s);
            }
        }
        dst[p] = s;
    }
}

// ---------------- pointwise 256->256 on g_z -> g_k (row-major) ----------------
__global__ void pw_kernel(const float* __restrict__ pwb)
{
    extern __shared__ float sm[];     // 256 x 64
    const int b = blockIdx.y, p0 = blockIdx.x * TP, t = threadIdx.x;
    float4* sm4 = (float4*)sm;
    for (int i = t; i < CC*16; i += 256) {
        int c = i >> 4, j = i & 15;
        sm4[i] = ((const float4*)(g_z + ((size_t)(b*CC + c))*HWW + p0))[j];
    }
    __syncthreads();

    float acc[TP];
    {
        float bias = pwb[t];
#pragma unroll
        for (int p = 0; p < TP; p++) acc[p] = bias;
    }
    float w = g_pwt[t];
    for (int c = 0; c < CC; c++) {
        float wn = (c + 1 < CC) ? g_pwt[(c+1)*CC + t] : 0.f;
        fma_row(acc, sm + c*TP, w);
        w = wn;
    }
#pragma unroll
    for (int p = 0; p < TP; p++)
        g_k[((size_t)(b*HWW + p0 + p))*CC + t] = acc[p];
}

// ---------------- attention: flash-style, 64q x 64k tiles, value dim 34 ----------------
// smem float offsets
#define A_OFF_K 16640            // Q: 64 rows * 260 (65 float4)
#define A_OFF_S 33280            // S: 64 rows * 68
#define A_OFF_P 37632            // Pos: 64 rows * 36
#define A_OFF_O 39936            // Oacc: 64 rows * 36
#define A_OFF_M 42240
#define A_OFF_L 42304
#define A_SMEM_FLOATS 42368      // *4 = 169472 bytes

__device__ __forceinline__ void softmax_pv(float* Ss, float* Pt, float* Oa,
                                           float* ms, float* ls, int r, int part, int kn)
{
    float* srow = Ss + r*68;
    float lm = -1e30f;
    for (int k = part; k < kn; k += 4) lm = fmaxf(lm, srow[k]);
    lm = fmaxf(lm, __shfl_xor_sync(0xffffffffu, lm, 1));
    lm = fmaxf(lm, __shfl_xor_sync(0xffffffffu, lm, 2));
    float mo = ms[r];
    float mn = fmaxf(mo, lm);
    float f  = __expf(mo - mn);
    float lsum = 0.f;
    for (int k = part; k < kn; k += 4) {
        float e = __expf(srow[k] - mn);
        srow[k] = e;
        lsum += e;
    }
    lsum += __shfl_xor_sync(0xffffffffu, lsum, 1);
    lsum += __shfl_xor_sync(0xffffffffu, lsum, 2);
    if (part == 0) { ls[r] = ls[r]*f + lsum; ms[r] = mn; }
    __syncwarp();   // srow[] writes from all 4 lanes of the group visible

    float* orow = Oa + r*36;
    float o[9];
#pragma unroll
    for (int idx = 0; idx < 9; idx++) {
        int d = part + 4*idx;
        o[idx] = (d < POSC) ? orow[d]*f : 0.f;
    }
    for (int k = 0; k < kn; k++) {
        float sv = srow[k];
        const float* prow = Pt + k*36;
#pragma unroll
        for (int idx = 0; idx < 9; idx++) {
            int d = part + 4*idx;
            if (d < POSC) o[idx] = fmaf(sv, prow[d], o[idx]);
        }
    }
#pragma unroll
    for (int idx = 0; idx < 9; idx++) {
        int d = part + 4*idx;
        if (d < POSC) orow[d] = o[idx];
    }
}

__global__ void attn_kernel(const float* __restrict__ dvec, const float* __restrict__ dpos,
                            float* __restrict__ out)
{
    extern __shared__ float sm[];
    const int b = blockIdx.y, q0 = blockIdx.x * 64, t = threadIdx.x;
    float* Qs = sm;
    float* Ks = sm + A_OFF_K;
    float* Ss = sm + A_OFF_S;
    float* Pt = sm + A_OFF_P;
    float* Oa = sm + A_OFF_O;
    float* ms = sm + A_OFF_M;
    float* ls = sm + A_OFF_L;
    float4* Q4 = (float4*)Qs;
    float4* K4 = (float4*)Ks;

    {   // load Q tile, pre-scaled by 1/sqrt(256)
        const float4* qsrc = (const float4*)(g_q + ((size_t)(b*HWW + q0))*CC);
        for (int i = t; i < 64*64; i += 256) {
            int r = i >> 6, j = i & 63;
            float4 v = qsrc[i];
            v.x *= 0.0625f; v.y *= 0.0625f; v.z *= 0.0625f; v.w *= 0.0625f;
            Q4[r*65 + j] = v;
        }
    }
    for (int i = t; i < 64*36; i += 256) Oa[i] = 0.f;
    if (t < 64) { ms[t] = -1e30f; ls[t] = 0.f; }
    __syncthreads();

    const int r    = t >> 2, part = t & 3;
    const int tq   = (t >> 4) << 2;
    const int tk   = (t & 15) << 2;

    for (int kt = 0; kt < 64; kt++) {
        {   // load K tile + Pos tile
            const float4* ksrc = (const float4*)(g_k + ((size_t)(b*HWW + kt*64))*CC);
            for (int i = t; i < 64*64; i += 256) {
                int rr = i >> 6, j = i & 63;
                K4[rr*65 + j] = ksrc[i];
            }
            const float* psrc = g_pos + ((size_t)(b*HWW + kt*64))*POSC;
            for (int i = t; i < 64*POSC; i += 256) {
                int rr = i / POSC, d = i - rr*POSC;
                Pt[rr*36 + d] = psrc[i];
            }
        }
        __syncthreads();

        // S = (Q/16) · K^T  — 4x4 register micro-tile per thread
        float s[4][4];
#pragma unroll
        for (int i = 0; i < 4; i++)
#pragma unroll
            for (int j = 0; j < 4; j++) s[i][j] = 0.f;

        const float4* qa = Q4 + tq*65;
        const float4* kb = K4 + tk*65;
#pragma unroll 2
        for (int j = 0; j < 64; j++) {
            float4 a0 = qa[0*65 + j], a1 = qa[1*65 + j], a2 = qa[2*65 + j], a3 = qa[3*65 + j];
            float4 b0 = kb[0*65 + j], b1 = kb[1*65 + j], b2 = kb[2*65 + j], b3 = kb[3*65 + j];
#define DOT4(SS, A, Bv) SS = fmaf(A.x, Bv.x, SS); SS = fmaf(A.y, Bv.y, SS); \
                        SS = fmaf(A.z, Bv.z, SS); SS = fmaf(A.w, Bv.w, SS);
            DOT4(s[0][0], a0, b0) DOT4(s[0][1], a0, b1) DOT4(s[0][2], a0, b2) DOT4(s[0][3], a0, b3)
            DOT4(s[1][0], a1, b0) DOT4(s[1][1], a1, b1) DOT4(s[1][2], a1, b2) DOT4(s[1][3], a1, b3)
            DOT4(s[2][0], a2, b0) DOT4(s[2][1], a2, b1) DOT4(s[2][2], a2, b2) DOT4(s[2][3], a2, b3)
            DOT4(s[3][0], a3, b0) DOT4(s[3][1], a3, b1) DOT4(s[3][2], a3, b2) DOT4(s[3][3], a3, b3)
#undef DOT4
        }
#pragma unroll
        for (int i = 0; i < 4; i++)
#pragma unroll
            for (int j = 0; j < 4; j++)
                Ss[(tq + i)*68 + tk + j] = s[i][j];
        __syncthreads();

        softmax_pv(Ss, Pt, Oa, ms, ls, r, part, 64);
        __syncthreads();
    }

    // dustbin token (kn = 1)
    {
        if (t < 64) K4[t] = ((const float4*)dvec)[t];
        if (t < POSC) Pt[t] = dpos[t];
        __syncthreads();
        if (t < 64) {
            float sdb = 0.f;
            const float4* qa2 = Q4 + t*65;
#pragma unroll 8
            for (int j = 0; j < 64; j++) {
                float4 a = qa2[j], bb = K4[j];
                sdb = fmaf(a.x, bb.x, sdb); sdb = fmaf(a.y, bb.y, sdb);
                sdb = fmaf(a.z, bb.z, sdb); sdb = fmaf(a.w, bb.w, sdb);
            }
            Ss[t*68] = sdb;
        }
        __syncthreads();
        softmax_pv(Ss, Pt, Oa, ms, ls, r, part, 1);
        __syncthreads();
    }

    // normalize + write output [b][34][64][64]
    for (int i = t; i < POSC*64; i += 256) {
        int d = i >> 6, rr = i & 63;
        out[((size_t)(b*POSC + d))*HWW + q0 + rr] = Oa[rr*36 + d] / ls[rr];
    }
}

// ---------------- launch ----------------
extern "C" void kernel_launch(void* const* d_in, const int* in_sizes, int n_in,
                              void* d_out, int out_size)
{
    const float* x      = (const float*)d_in[0];
    const float* y      = (const float*)d_in[1];
    const float* feat1  = (const float*)d_in[2];
    const float* feat2  = (const float*)d_in[3];
    const float* pg_w1  = (const float*)d_in[4];
    const float* pg_b1  = (const float*)d_in[5];
    const float* pg_w2  = (const float*)d_in[6];
    const float* pg_b2  = (const float*)d_in[7];
    const float* fus_w1 = (const float*)d_in[8];
    const float* fus_b1 = (const float*)d_in[9];
    const float* fus_w2 = (const float*)d_in[10];
    const float* fus_b2 = (const float*)d_in[11];
    const float* dw_w   = (const float*)d_in[12];
    const float* dw_b   = (const float*)d_in[13];
    const float* pw_w   = (const float*)d_in[14];
    const float* pw_b   = (const float*)d_in[15];
    const float* dvec   = (const float*)d_in[16];
    const float* dpos   = (const float*)d_in[17];
    float* out = (float*)d_out;

    cudaFuncSetAttribute(fuser_kernel, cudaFuncAttributeMaxDynamicSharedMemorySize, 98304);
    cudaFuncSetAttribute(pw_kernel,    cudaFuncAttributeMaxDynamicSharedMemorySize, 65536);
    cudaFuncSetAttribute(attn_kernel,  cudaFuncAttributeMaxDynamicSharedMemorySize, A_SMEM_FLOATS*4);

    prep_weights<<<977, 256>>>(fus_w1, fus_w2, pw_w, pg_w1, pg_w2);
    fuser_kernel<<<dim3(64, BB), 256, 98304>>>(x, feat1, fus_b1, fus_b2, 0);
    fuser_kernel<<<dim3(64, BB), 256, 98304>>>(y, feat2, fus_b1, fus_b2, 1);
    posgen_kernel<<<dim3(64, BB), 128, 34816>>>(feat2, pg_b1, pg_b2);
    dw_kernel<<<dim3(256, BB), 256>>>(dw_w, dw_b);
    pw_kernel<<<dim3(64, BB), 256, 65536>>>(pw_b);
    attn_kernel<<<dim3(64, BB), 256, A_SMEM_FLOATS*4>>>(dvec, dpos, out);
}

// round 4
// speedup vs baseline: 3.5868x; 3.5868x over previous
#include <cuda_runtime.h>
#include <cuda_bf16.h>
#include <math.h>

#define BB   8
#define CC   256
#define FDD  128
#define HWW  4096
#define POSC 34
#define IN1  384
#define TP   64

// ---------------- device-global scratch (no runtime allocation) ----------------
__device__ float g_q  [BB*HWW*CC];     // [b][p][256] row-major (queries, fused x)
__device__ float g_yf [BB*CC*HWW];     // [b][c][p]
__device__ float g_z  [BB*CC*HWW];     // [b][c][p] after dw3x3
// K tiles, xor-swizzled bf16 blobs: per (b,kt): 64 keys x 512B (256 ch)
__device__ __nv_bfloat16 g_khi[(size_t)BB*64*16384];
__device__ __nv_bfloat16 g_klo[(size_t)BB*64*16384];
// posT tiles: per (b,kt): 40 dims x 128B (64 keys)
__device__ __nv_bfloat16 g_pthi[(size_t)BB*64*2560];
__device__ __nv_bfloat16 g_ptlo[(size_t)BB*64*2560];
__device__ float g_w1t  [IN1*CC];
__device__ float g_w2t  [CC*CC];
__device__ float g_pwt  [CC*CC];
__device__ float g_pgw1t[130*FDD];
__device__ float g_pgw2t[FDD*32];

// ================= PTX helpers (baseline features only) =================
__device__ __forceinline__ unsigned smem_u32(const void* p) {
    unsigned a;
    asm("{ .reg .u64 t; cvta.to.shared.u64 t, %1; cvt.u32.u64 %0, t; }" : "=r"(a) : "l"(p));
    return a;
}
__device__ __forceinline__ void ldsm4(unsigned* r, unsigned addr) {
    asm volatile("ldmatrix.sync.aligned.m8n8.x4.shared.b16 {%0,%1,%2,%3}, [%4];"
        : "=r"(r[0]), "=r"(r[1]), "=r"(r[2]), "=r"(r[3]) : "r"(addr));
}
__device__ __forceinline__ void ldsm2(unsigned* r, unsigned addr) {
    asm volatile("ldmatrix.sync.aligned.m8n8.x2.shared.b16 {%0,%1}, [%2];"
        : "=r"(r[0]), "=r"(r[1]) : "r"(addr));
}
__device__ __forceinline__ void mma16816(float* c, const unsigned* a, unsigned b0, unsigned b1) {
    asm volatile("mma.sync.aligned.m16n8k16.row.col.f32.bf16.bf16.f32 "
        "{%0,%1,%2,%3}, {%4,%5,%6,%7}, {%8,%9}, {%0,%1,%2,%3};"
        : "+f"(c[0]), "+f"(c[1]), "+f"(c[2]), "+f"(c[3])
        : "r"(a[0]), "r"(a[1]), "r"(a[2]), "r"(a[3]), "r"(b0), "r"(b1));
}
__device__ __forceinline__ unsigned pack_bf16x2(float a, float b, float* ra, float* rb) {
    __nv_bfloat162 h = __floats2bfloat162_rn(a, b);
    *ra = a - __low2float(h);
    *rb = b - __high2float(h);
    union { __nv_bfloat162 h; unsigned u; } cv; cv.h = h;
    return cv.u;
}

// ---------------- weight transposes ----------------
__global__ void prep_weights(const float* __restrict__ fw1, const float* __restrict__ fw2,
                             const float* __restrict__ pww, const float* __restrict__ pgw1,
                             const float* __restrict__ pgw2)
{
    int i = blockIdx.x * 256 + threadIdx.x;
    if (i < 256*384) { int o = i / 384, c = i % 384; g_w1t[c*256 + o] = fw1[i]; return; }
    i -= 256*384;
    if (i < 256*256) { int o = i >> 8, c = i & 255; g_w2t[c*256 + o] = fw2[i]; return; }
    i -= 65536;
    if (i < 256*256) { int o = i >> 8, c = i & 255; g_pwt[c*256 + o] = pww[i]; return; }
    i -= 65536;
    if (i < 128*130) { int o = i / 130, c = i % 130; g_pgw1t[c*128 + o] = pgw1[i]; return; }
    i -= 16640;
    if (i < 32*128)  { int o = i >> 7, c = i & 127; g_pgw2t[c*32 + o] = pgw2[i]; return; }
}

__device__ __forceinline__ void fma_row(float* acc, const float* row, float w)
{
    const float4* r4 = (const float4*)row;
#pragma unroll
    for (int j = 0; j < 16; j++) {
        float4 v = r4[j];
        acc[4*j+0] = fmaf(w, v.x, acc[4*j+0]);
        acc[4*j+1] = fmaf(w, v.y, acc[4*j+1]);
        acc[4*j+2] = fmaf(w, v.z, acc[4*j+2]);
        acc[4*j+3] = fmaf(w, v.w, acc[4*j+3]);
    }
}

// ---------------- fuser ----------------
__global__ void fuser_kernel(const float* __restrict__ xin, const float* __restrict__ feat,
                             const float* __restrict__ b1, const float* __restrict__ b2,
                             int mode)
{
    extern __shared__ float sm[];
    const int b  = blockIdx.y;
    const int p0 = blockIdx.x * TP;
    const int t  = threadIdx.x;

    float4* sm4 = (float4*)sm;
    for (int i = t; i < IN1*16; i += 256) {
        int c = i >> 4, j = i & 15;
        const float* src = (c < CC) ? (xin  + ((size_t)(b*CC  + c     ))*HWW + p0)
                                    : (feat + ((size_t)(b*FDD + (c-CC)))*HWW + p0);
        sm4[i] = ((const float4*)src)[j];
    }
    __syncthreads();

    float acc[TP];
    {
        float bias = b1[t];
#pragma unroll
        for (int p = 0; p < TP; p++) acc[p] = bias;
    }
    float w = g_w1t[t];
    for (int c = 0; c < IN1; c++) {
        float wn = (c + 1 < IN1) ? g_w1t[(c+1)*CC + t] : 0.f;
        fma_row(acc, sm + c*TP, w);
        w = wn;
    }
    __syncthreads();
#pragma unroll
    for (int p = 0; p < TP; p++) sm[t*68 + p] = fmaxf(acc[p], 0.f);
    __syncthreads();

    float acc2[TP];
    {
        float bias = b2[t];
#pragma unroll
        for (int p = 0; p < TP; p++) acc2[p] = bias;
    }
    w = g_w2t[t];
    for (int h = 0; h < CC; h++) {
        float wn = (h + 1 < CC) ? g_w2t[(h+1)*CC + t] : 0.f;
        fma_row(acc2, sm + h*68, w);
        w = wn;
    }

    if (mode == 0) {
#pragma unroll
        for (int p = 0; p < TP; p++)
            g_q[((size_t)(b*HWW + p0 + p))*CC + t] = acc2[p];
    } else {
        __syncthreads();
#pragma unroll
        for (int p = 0; p < TP; p++) sm[t*68 + p] = acc2[p];
        __syncthreads();
        for (int i = t; i < CC*TP; i += 256) {
            int c = i >> 6, p = i & 63;
            g_yf[((size_t)(b*CC + c))*HWW + p0 + p] = sm[c*68 + p];
        }
    }
}

// ---------------- pos_gen -> V^T bf16 split blobs [40 dims][64 keys], xor swizzle ----------------
__global__ void posgen_kernel(const float* __restrict__ feat2,
                              const float* __restrict__ b1, const float* __restrict__ b2)
{
    extern __shared__ float sm[];   // [0,8704) floats: input/H ; [8704, 11264): bf16 stage
    const int b   = blockIdx.y;
    const int row = blockIdx.x;       // image row == key-tile index kt
    const int p0  = row * 64;
    const int t   = threadIdx.x;      // 128 threads
    const float gy = -1.f + 2.f * row * (1.f/63.f);

    __nv_bfloat16* vh = (__nv_bfloat16*)(sm + 8704);
    __nv_bfloat16* vl = vh + 2560;

    // rows 34..39 zero; rows 32/33 raw grid (independent of MLP)
    if (t >= 34 && t < 40) {
        unsigned xo = (unsigned)((t & 7) << 4);
        for (int p = 0; p < 64; p++) {
            unsigned off = ((unsigned)t*128u + (((unsigned)(2*p)) ^ xo)) >> 1;
            vh[off] = __float2bfloat16(0.f); vl[off] = __float2bfloat16(0.f);
        }
    } else if (t == 32 || t == 33) {
        unsigned xo = (unsigned)((t & 7) << 4);
        for (int p = 0; p < 64; p++) {
            float v = (t == 32) ? (-1.f + 2.f * p * (1.f/63.f)) : gy;
            float ra, rb;
            unsigned u = pack_bf16x2(v, 0.f, &ra, &rb);
            __nv_bfloat16 h = __ushort_as_bfloat16((unsigned short)(u & 0xFFFF));
            unsigned off = ((unsigned)t*128u + (((unsigned)(2*p)) ^ xo)) >> 1;
            vh[off] = h; vl[off] = __float2bfloat16(ra);
        }
    }

    for (int i = t; i < 130*64; i += 128) {
        int c = i >> 6, p = i & 63;
        float v;
        if (c == 0)      v = 1.f + (-1.f + 2.f * p * (1.f/63.f));
        else if (c == 1) v = 1.f + gy;
        else             v = feat2[((size_t)(b*FDD + (c-2)))*HWW + p0 + p];
        sm[i] = v;
    }
    __syncthreads();

    float acc[64];
    {
        float bias = b1[t];
#pragma unroll
        for (int p = 0; p < 64; p++) acc[p] = bias;
    }
    float w = g_pgw1t[t];
    for (int c = 0; c < 130; c++) {
        float wn = (c + 1 < 130) ? g_pgw1t[(c+1)*FDD + t] : 0.f;
        fma_row(acc, sm + c*64, w);
        w = wn;
    }
    __syncthreads();
#pragma unroll
    for (int p = 0; p < 64; p++) sm[t*68 + p] = fmaxf(acc[p], 0.f);
    __syncthreads();

    if (t < 32) {
        float acc2[64];
        float bias = b2[t];
#pragma unroll
        for (int p = 0; p < 64; p++) acc2[p] = bias;
        float w2 = g_pgw2t[t];
        for (int h = 0; h < FDD; h++) {
            float wn = (h + 1 < FDD) ? g_pgw2t[(h+1)*32 + t] : 0.f;
            fma_row(acc2, sm + h*68, w2);
            w2 = wn;
        }
        unsigned xo = (unsigned)((t & 7) << 4);
#pragma unroll 8
        for (int p = 0; p < 64; p++) {
            float v = fmaxf(acc2[p], 0.f);
            __nv_bfloat16 h = __float2bfloat16(v);
            float lo = v - __bfloat162float(h);
            unsigned off = ((unsigned)t*128u + (((unsigned)(2*p)) ^ xo)) >> 1;
            vh[off] = h; vl[off] = __float2bfloat16(lo);
        }
    }
    __syncthreads();

    // blob out (coalesced)
    const size_t tb = ((size_t)(b*64 + row)) * 2560;
    float4* dh = (float4*)(g_pthi + tb);
    float4* dl = (float4*)(g_ptlo + tb);
    for (int i = t; i < 320; i += 128) { dh[i] = ((float4*)vh)[i]; dl[i] = ((float4*)vl)[i]; }
}

// ---------------- depthwise 3x3 ----------------
__global__ void dw_kernel(const float* __restrict__ dww, const float* __restrict__ dwb)
{
    __shared__ float plane[HWW];
    const int c = blockIdx.x, b = blockIdx.y, t = threadIdx.x;
    const float* src = g_yf + ((size_t)(b*CC + c))*HWW;
    float4* p4 = (float4*)plane;
    for (int i = t; i < HWW/4; i += 256) p4[i] = ((const float4*)src)[i];
    float w[9];
#pragma unroll
    for (int i = 0; i < 9; i++) w[i] = __ldg(dww + c*9 + i);
    const float bias = __ldg(dwb + c);
    __syncthreads();

    float* dst = g_z + ((size_t)(b*CC + c))*HWW;
#pragma unroll
    for (int ii = 0; ii < 16; ii++) {
        int p  = t + ii*256;
        int py = p >> 6, px = p & 63;
        float s = bias;
#pragma unroll
        for (int dy = -1; dy <= 1; dy++) {
            int iy = py + dy;
            if (iy < 0 || iy > 63) continue;
#pragma unroll
            for (int dx = -1; dx <= 1; dx++) {
                int ix = px + dx;
                if (ix < 0 || ix > 63) continue;
                s = fmaf(plane[iy*64 + ix], w[(dy+1)*3 + (dx+1)], s);
            }
        }
        dst[p] = s;
    }
}

// ---------------- pointwise 256->256 -> K bf16 split blobs [64 keys][256 ch], xor swizzle --------
__global__ void pw_kernel(const float* __restrict__ pwb)
{
    extern __shared__ float sm[];   // 16384 floats: inputs, then reused as bf16 stage (hi 32KB | lo 32KB)
    const int b = blockIdx.y, kt = blockIdx.x, p0 = kt * TP, t = threadIdx.x;
    float4* sm4 = (float4*)sm;
    for (int i = t; i < CC*16; i += 256) {
        int c = i >> 4, j = i & 15;
        sm4[i] = ((const float4*)(g_z + ((size_t)(b*CC + c))*HWW + p0))[j];
    }
    __syncthreads();

    float acc[TP];
    {
        float bias = pwb[t];
#pragma unroll
        for (int p = 0; p < TP; p++) acc[p] = bias;
    }
    float w = g_pwt[t];
    for (int c = 0; c < CC; c++) {
        float wn = (c + 1 < CC) ? g_pwt[(c+1)*CC + t] : 0.f;
        fma_row(acc, sm + c*TP, w);
        w = wn;
    }
    __syncthreads();

    // stage swizzled bf16 tiles: row = key p, 512B/row; chunk xor (p&7)<<4
    __nv_bfloat16* sh = (__nv_bfloat16*)sm;
    __nv_bfloat16* sl = sh + 16384;
#pragma unroll 8
    for (int p = 0; p < TP; p++) {
        float v = acc[p];
        __nv_bfloat16 h = __float2bfloat16(v);
        float lo = v - __bfloat162float(h);
        unsigned off = ((unsigned)p*512u + (((unsigned)(2*t)) ^ ((unsigned)((p & 7) << 4)))) >> 1;
        sh[off] = h; sl[off] = __float2bfloat16(lo);
    }
    __syncthreads();

    const size_t tb = ((size_t)(b*64 + kt)) * 16384;
    float4* dh = (float4*)(g_khi + tb);
    float4* dl = (float4*)(g_klo + tb);
    for (int i = t; i < 2048; i += 256) { dh[i] = ((float4*)sh)[i]; dl[i] = ((float4*)sl)[i]; }
}

// ---------------- attention: mma.sync bf16-split flash attention ----------------
// smem byte offsets
#define A_QHI 0
#define A_QLO 65536
#define A_KHI 131072
#define A_KLO 163840
#define A_VHI 196608
#define A_VLO 201728
#define A_DVEC 206848
#define A_DPOS 207872
#define ATT_SMEM 208064

__global__ void __launch_bounds__(256, 1)
attn_kernel(const float* __restrict__ dvec, const float* __restrict__ dpos,
            float* __restrict__ out)
{
    extern __shared__ char smc[];
    const unsigned sb = smem_u32(smc);

    const int b = blockIdx.y, q0 = blockIdx.x * 128;
    const int tid = threadIdx.x, w = tid >> 5, l = tid & 31;
    const int g = l >> 2, qd = l & 3;
    const int R = w * 16;

    float* dvs = (float*)(smc + A_DVEC);
    float* dps = (float*)(smc + A_DPOS);
    if (tid < 64) ((float4*)dvs)[tid] = ((const float4*)dvec)[tid];
    if (tid < 40) dps[tid] = (tid < POSC) ? dpos[tid] : 0.f;

    // ---- stage Q (scaled 1/16, split bf16, xor swizzle) ----
    for (int i = tid; i < 16384; i += 256) {
        int row = i >> 7, cp = i & 127;
        const float* qr = g_q + ((size_t)(b*HWW + q0 + row))*CC + 2*cp;
        float v0 = qr[0] * 0.0625f, v1 = qr[1] * 0.0625f;
        float ra, rb;
        unsigned hu = pack_bf16x2(v0, v1, &ra, &rb);
        float dum0, dum1;
        unsigned lu = pack_bf16x2(ra, rb, &dum0, &dum1);
        unsigned off = (unsigned)row*512u + (((unsigned)(4*cp)) ^ ((unsigned)((row & 7) << 4)));
        *(unsigned*)(smc + A_QHI + off) = hu;
        *(unsigned*)(smc + A_QLO + off) = lu;
    }
    __syncthreads();

    // lane-constant ldmatrix address terms
    const int mrow = l & 7, msel = l >> 3;
    const unsigned rowA  = (unsigned)(R + mrow + (msel & 1) * 8);
    const unsigned aBase = rowA * 512u;
    const unsigned aChS  = (unsigned)((msel >> 1) << 4);
    const unsigned aXor  = (rowA & 7u) << 4;
    const unsigned keyoff = (unsigned)(((msel >> 1) << 3) + mrow);   // 0..15
    const unsigned bChS  = (unsigned)((msel & 1) << 4);
    const unsigned bXor  = (keyoff & 7u) << 4;
    const int lm = l & 15;
    const unsigned dim2   = (unsigned)(32 + (lm & 7));
    const unsigned v2ChS  = (unsigned)(((lm >> 3) & 1) << 4);
    const unsigned v2Xor  = ((unsigned)(lm & 7)) << 4;

    float Oa[5][4];
#pragma unroll
    for (int n = 0; n < 5; n++)
#pragma unroll
        for (int c = 0; c < 4; c++) Oa[n][c] = 0.f;
    float mr0 = -1e30f, mr1 = -1e30f, lr0 = 0.f, lr1 = 0.f;

    for (int kt = 0; kt < 64; kt++) {
        // -- stage K / V blobs (pre-swizzled) --
        {
            const size_t tb = ((size_t)(b*64 + kt));
            const float4* skh = ((const float4*)g_khi)  + tb*2048;
            const float4* skl = ((const float4*)g_klo)  + tb*2048;
            const float4* svh = ((const float4*)g_pthi) + tb*320;
            const float4* svl = ((const float4*)g_ptlo) + tb*320;
            float4* dkh = (float4*)(smc + A_KHI);
            float4* dkl = (float4*)(smc + A_KLO);
            float4* dvh = (float4*)(smc + A_VHI);
            float4* dvl = (float4*)(smc + A_VLO);
            for (int i = tid; i < 2048; i += 256) { dkh[i] = skh[i]; dkl[i] = skl[i]; }
            for (int i = tid; i < 320;  i += 256) { dvh[i] = svh[i]; dvl[i] = svl[i]; }
        }
        __syncthreads();

        // -- S = Qs·K^T (3 split terms) --
        float sacc[8][4];
#pragma unroll
        for (int j = 0; j < 8; j++)
#pragma unroll
            for (int c = 0; c < 4; c++) sacc[j][c] = 0.f;

#pragma unroll 4
        for (int s = 0; s < 16; s++) {
            unsigned ah[4], al[4];
            unsigned aoff = aBase + ((((unsigned)s << 5) | aChS) ^ aXor);
            ldsm4(ah, sb + A_QHI + aoff);
            ldsm4(al, sb + A_QLO + aoff);
            unsigned bh[16], bl[16];
#pragma unroll
            for (int jp = 0; jp < 4; jp++) {
                unsigned ka = ((unsigned)(16*jp) + keyoff)*512u + ((((unsigned)s << 5) | bChS) ^ bXor);
                ldsm4(bh + 4*jp, sb + A_KHI + ka);
                ldsm4(bl + 4*jp, sb + A_KLO + ka);
            }
#pragma unroll
            for (int jp = 0; jp < 4; jp++) {
                mma16816(sacc[2*jp],   ah, bh[4*jp],   bh[4*jp+1]);
                mma16816(sacc[2*jp+1], ah, bh[4*jp+2], bh[4*jp+3]);
                mma16816(sacc[2*jp],   ah, bl[4*jp],   bl[4*jp+1]);
                mma16816(sacc[2*jp+1], ah, bl[4*jp+2], bl[4*jp+3]);
                mma16816(sacc[2*jp],   al, bh[4*jp],   bh[4*jp+1]);
                mma16816(sacc[2*jp+1], al, bh[4*jp+2], bh[4*jp+3]);
            }
        }

        // -- online softmax (register, quad reduce) --
        float m0 = -1e30f, m1 = -1e30f;
#pragma unroll
        for (int j = 0; j < 8; j++) {
            m0 = fmaxf(m0, fmaxf(sacc[j][0], sacc[j][1]));
            m1 = fmaxf(m1, fmaxf(sacc[j][2], sacc[j][3]));
        }
        m0 = fmaxf(m0, __shfl_xor_sync(0xffffffffu, m0, 1));
        m0 = fmaxf(m0, __shfl_xor_sync(0xffffffffu, m0, 2));
        m1 = fmaxf(m1, __shfl_xor_sync(0xffffffffu, m1, 1));
        m1 = fmaxf(m1, __shfl_xor_sync(0xffffffffu, m1, 2));
        float mn0 = fmaxf(mr0, m0), mn1 = fmaxf(mr1, m1);
        float f0 = __expf(mr0 - mn0), f1 = __expf(mr1 - mn1);
        float ls0 = 0.f, ls1 = 0.f;
#pragma unroll
        for (int j = 0; j < 8; j++) {
            float e;
            e = __expf(sacc[j][0] - mn0); sacc[j][0] = e; ls0 += e;
            e = __expf(sacc[j][1] - mn0); sacc[j][1] = e; ls0 += e;
            e = __expf(sacc[j][2] - mn1); sacc[j][2] = e; ls1 += e;
            e = __expf(sacc[j][3] - mn1); sacc[j][3] = e; ls1 += e;
        }
        ls0 += __shfl_xor_sync(0xffffffffu, ls0, 1);
        ls0 += __shfl_xor_sync(0xffffffffu, ls0, 2);
        ls1 += __shfl_xor_sync(0xffffffffu, ls1, 1);
        ls1 += __shfl_xor_sync(0xffffffffu, ls1, 2);
        mr0 = mn0; mr1 = mn1;
        lr0 = lr0*f0 + ls0; lr1 = lr1*f1 + ls1;
#pragma unroll
        for (int n = 0; n < 5; n++) {
            Oa[n][0] *= f0; Oa[n][1] *= f0; Oa[n][2] *= f1; Oa[n][3] *= f1;
        }

        // -- O += P·V (P re-packed from sacc as A fragments; 3 split terms) --
#pragma unroll
        for (int s = 0; s < 4; s++) {
            unsigned ahp[4], alp[4];
            float r0a, r0b, r1a, r1b;
            ahp[0] = pack_bf16x2(sacc[2*s][0],   sacc[2*s][1],   &r0a, &r0b);
            alp[0] = pack_bf16x2(r0a, r0b, &r1a, &r1b);
            ahp[1] = pack_bf16x2(sacc[2*s][2],   sacc[2*s][3],   &r0a, &r0b);
            alp[1] = pack_bf16x2(r0a, r0b, &r1a, &r1b);
            ahp[2] = pack_bf16x2(sacc[2*s+1][0], sacc[2*s+1][1], &r0a, &r0b);
            alp[2] = pack_bf16x2(r0a, r0b, &r1a, &r1b);
            ahp[3] = pack_bf16x2(sacc[2*s+1][2], sacc[2*s+1][3], &r0a, &r0b);
            alp[3] = pack_bf16x2(r0a, r0b, &r1a, &r1b);

            unsigned vh[8], vl[8], vh2[2], vl2[2];
#pragma unroll
            for (int jp = 0; jp < 2; jp++) {
                unsigned va = ((unsigned)(16*jp) + keyoff)*128u + ((((unsigned)s << 5) | bChS) ^ bXor);
                ldsm4(vh + 4*jp, sb + A_VHI + va);
                ldsm4(vl + 4*jp, sb + A_VLO + va);
            }
            unsigned va2 = dim2*128u + ((((unsigned)s << 5) | v2ChS) ^ v2Xor);
            ldsm2(vh2, sb + A_VHI + va2);
            ldsm2(vl2, sb + A_VLO + va2);

            mma16816(Oa[0], ahp, vh[0], vh[1]);
            mma16816(Oa[1], ahp, vh[2], vh[3]);
            mma16816(Oa[2], ahp, vh[4], vh[5]);
            mma16816(Oa[3], ahp, vh[6], vh[7]);
            mma16816(Oa[4], ahp, vh2[0], vh2[1]);
            mma16816(Oa[0], ahp, vl[0], vl[1]);
            mma16816(Oa[1], ahp, vl[2], vl[3]);
            mma16816(Oa[2], ahp, vl[4], vl[5]);
            mma16816(Oa[3], ahp, vl[6], vl[7]);
            mma16816(Oa[4], ahp, vl2[0], vl2[1]);
            mma16816(Oa[0], alp, vh[0], vh[1]);
            mma16816(Oa[1], alp, vh[2], vh[3]);
            mma16816(Oa[2], alp, vh[4], vh[5]);
            mma16816(Oa[3], alp, vh[6], vh[7]);
            mma16816(Oa[4], alp, vh2[0], vh2[1]);
        }
        __syncthreads();
    }

    // ---- dustbin token (fp32) + epilogue ----
    {
        const int r0 = q0 + R + g, r1 = r0 + 8;
        const float4* q0p = (const float4*)(g_q + ((size_t)(b*HWW + r0))*CC + 64*qd);
        const float4* q1p = (const float4*)(g_q + ((size_t)(b*HWW + r1))*CC + 64*qd);
        const float4* dv4 = ((const float4*)dvs) + 16*qd;
        float d0 = 0.f, d1 = 0.f;
#pragma unroll 8
        for (int j = 0; j < 16; j++) {
            float4 a0 = q0p[j], a1 = q1p[j], bv = dv4[j];
            d0 = fmaf(a0.x, bv.x, d0); d0 = fmaf(a0.y, bv.y, d0);
            d0 = fmaf(a0.z, bv.z, d0); d0 = fmaf(a0.w, bv.w, d0);
            d1 = fmaf(a1.x, bv.x, d1); d1 = fmaf(a1.y, bv.y, d1);
            d1 = fmaf(a1.z, bv.z, d1); d1 = fmaf(a1.w, bv.w, d1);
        }
        d0 += __shfl_xor_sync(0xffffffffu, d0, 1);
        d0 += __shfl_xor_sync(0xffffffffu, d0, 2);
        d1 += __shfl_xor_sync(0xffffffffu, d1, 1);
        d1 += __shfl_xor_sync(0xffffffffu, d1, 2);
        float s0 = d0 * 0.0625f, s1 = d1 * 0.0625f;
        float mn0 = fmaxf(mr0, s0), mn1 = fmaxf(mr1, s1);
        float f0 = __expf(mr0 - mn0), f1 = __expf(mr1 - mn1);
        float p0 = __expf(s0 - mn0),  p1 = __expf(s1 - mn1);
        lr0 = lr0*f0 + p0; lr1 = lr1*f1 + p1;
        float inv0 = 1.f / lr0, inv1 = 1.f / lr1;

#pragma unroll
        for (int n = 0; n < 5; n++) {
            int d = 8*n + 2*qd;
            if (d < POSC) {
                float v0 = (Oa[n][0]*f0 + p0*dps[d]) * inv0;
                float v2 = (Oa[n][2]*f1 + p1*dps[d]) * inv1;
                out[((size_t)(b*POSC + d))*HWW + r0] = v0;
                out[((size_t)(b*POSC + d))*HWW + r1] = v2;
            }
            if (d + 1 < POSC) {
                float v1 = (Oa[n][1]*f0 + p0*dps[d+1]) * inv0;
                float v3 = (Oa[n][3]*f1 + p1*dps[d+1]) * inv1;
                out[((size_t)(b*POSC + d+1))*HWW + r0] = v1;
                out[((size_t)(b*POSC + d+1))*HWW + r1] = v3;
            }
        }
    }
}

// ---------------- launch ----------------
extern "C" void kernel_launch(void* const* d_in, const int* in_sizes, int n_in,
                              void* d_out, int out_size)
{
    const float* x      = (const float*)d_in[0];
    const float* y      = (const float*)d_in[1];
    const float* feat1  = (const float*)d_in[2];
    const float* feat2  = (const float*)d_in[3];
    const float* pg_w1  = (const float*)d_in[4];
    const float* pg_b1  = (const float*)d_in[5];
    const float* pg_w2  = (const float*)d_in[6];
    const float* pg_b2  = (const float*)d_in[7];
    const float* fus_w1 = (const float*)d_in[8];
    const float* fus_b1 = (const float*)d_in[9];
    const float* fus_w2 = (const float*)d_in[10];
    const float* fus_b2 = (const float*)d_in[11];
    const float* dw_w   = (const float*)d_in[12];
    const float* dw_b   = (const float*)d_in[13];
    const float* pw_w   = (const float*)d_in[14];
    const float* pw_b   = (const float*)d_in[15];
    const float* dvec   = (const float*)d_in[16];
    const float* dpos   = (const float*)d_in[17];
    float* out = (float*)d_out;

    cudaFuncSetAttribute(fuser_kernel, cudaFuncAttributeMaxDynamicSharedMemorySize, 98304);
    cudaFuncSetAttribute(pw_kernel,    cudaFuncAttributeMaxDynamicSharedMemorySize, 65536);
    cudaFuncSetAttribute(attn_kernel,  cudaFuncAttributeMaxDynamicSharedMemorySize, ATT_SMEM);

    prep_weights<<<977, 256>>>(fus_w1, fus_w2, pw_w, pg_w1, pg_w2);
    fuser_kernel<<<dim3(64, BB), 256, 98304>>>(x, feat1, fus_b1, fus_b2, 0);
    fuser_kernel<<<dim3(64, BB), 256, 98304>>>(y, feat2, fus_b1, fus_b2, 1);
    posgen_kernel<<<dim3(64, BB), 128, 46080>>>(feat2, pg_b1, pg_b2);
    dw_kernel<<<dim3(256, BB), 256>>>(dw_w, dw_b);
    pw_kernel<<<dim3(64, BB), 256, 65536>>>(pw_b);
    attn_kernel<<<dim3(32, BB), 256, ATT_SMEM>>>(dvec, dpos, out);
}